// round 3
// baseline (speedup 1.0000x reference)
#include <cuda_runtime.h>

// y[b,t,c*S+s] = x[b,t,c] * w[c*S+s]
// B=512, T=128, C=128, S=32, OUT_DIM=4096. Output = 1 GiB fp32, write-bound.
//
// R3: each block produces 8 output rows (8192 float4s). w lives in REGISTERS:
// with pos = k*256+tid, (pos & 1023) has period 4 in k, so each thread needs
// only 4 distinct w float4s, loaded once per block. x (1024 floats) staged in
// shared. Store loop = broadcast LDS + FMUL + STG.128, nothing else.

#define ROWS_PER_BLOCK 8
#define THREADS        256
#define F4_PER_BLOCK   (ROWS_PER_BLOCK * 1024)   // 8192 float4s
#define ITERS          (F4_PER_BLOCK / THREADS)  // 32

__global__ __launch_bounds__(THREADS, 8)
void csi_embedding_kernel(const float*  __restrict__ x,
                          const float4* __restrict__ w4,
                          float4*       __restrict__ out4)
{
    __shared__ float s_x[ROWS_PER_BLOCK * 128];  // 4 KiB: x for 8 rows

    const int tid = threadIdx.x;

    // w into registers: thread's 4 distinct float4s (period-4 pattern in k)
    float4 wr0 = __ldg(&w4[0 * THREADS + tid]);
    float4 wr1 = __ldg(&w4[1 * THREADS + tid]);
    float4 wr2 = __ldg(&w4[2 * THREADS + tid]);
    float4 wr3 = __ldg(&w4[3 * THREADS + tid]);

    // Stage x: 1024 consecutive floats = rows [8*bid .. 8*bid+7], coalesced
    const int xbase = blockIdx.x * (ROWS_PER_BLOCK * 128);
    #pragma unroll
    for (int k = 0; k < 4; k++)
        s_x[k * THREADS + tid] = __ldg(&x[xbase + k * THREADS + tid]);

    __syncthreads();

    const long long base = (long long)blockIdx.x * F4_PER_BLOCK;

    #pragma unroll
    for (int k = 0; k < ITERS; k++) {
        // pos = k*256 + tid; x index = pos>>3 = k*32 + (tid>>3)
        float xs = s_x[k * 32 + (tid >> 3)];     // broadcast across 8 lanes

        float4 wv;
        switch (k & 3) {                          // resolved at compile time
            case 0: wv = wr0; break;
            case 1: wv = wr1; break;
            case 2: wv = wr2; break;
            default: wv = wr3; break;
        }

        float4 r;
        r.x = xs * wv.x;
        r.y = xs * wv.y;
        r.z = xs * wv.z;
        r.w = xs * wv.w;
        __stcs(&out4[base + k * THREADS + tid], r);
    }
}

extern "C" void kernel_launch(void* const* d_in, const int* in_sizes, int n_in,
                              void* d_out, int out_size)
{
    const float*  x  = (const float*)d_in[0];
    const float4* w4 = (const float4*)d_in[1];
    float4* out4 = (float4*)d_out;

    // out_size = 512*128*4096 floats -> /4 -> /8192 per block = 8192 blocks
    int blocks = (out_size / 4) / F4_PER_BLOCK;
    csi_embedding_kernel<<<blocks, THREADS>>>(x, w4, out4);
}

// round 4
// speedup vs baseline: 1.0340x; 1.0340x over previous
#include <cuda_runtime.h>

// y[b,t,c*S+s] = x[b,t,c] * w[c*S+s]
// B=512, T=128, C=128, S=32, OUT_DIM=4096. Output = 1 GiB fp32, write-bound.
//
// R4 = R2 geometry (2 rows/block, 256 thr, 32768 blocks — fine-grained grid
// smooths the DRAM write stream; 27.7 waves) + w in registers: with
// pos = k*256+tid, (pos & 1023) has period 4 over k=0..7, so each thread needs
// exactly 4 w float4s, loaded once. No s_w, no per-iteration w LDS traffic.

#define ROWS_PER_BLOCK 2
#define THREADS        256
#define F4_PER_BLOCK   (ROWS_PER_BLOCK * 1024)   // 2048 float4s
#define ITERS          (F4_PER_BLOCK / THREADS)  // 8

__global__ __launch_bounds__(THREADS, 8)
void csi_embedding_kernel(const float*  __restrict__ x,
                          const float4* __restrict__ w4,
                          float4*       __restrict__ out4)
{
    __shared__ float s_x[ROWS_PER_BLOCK * 128];  // 1 KiB: x for 2 rows

    const int tid = threadIdx.x;

    // w into registers (L1/L2-hit after first blocks): 4 distinct float4s
    float4 wr0 = __ldg(&w4[0 * THREADS + tid]);
    float4 wr1 = __ldg(&w4[1 * THREADS + tid]);
    float4 wr2 = __ldg(&w4[2 * THREADS + tid]);
    float4 wr3 = __ldg(&w4[3 * THREADS + tid]);

    // Stage x: 256 consecutive floats = rows [2*bid, 2*bid+1], coalesced
    s_x[tid] = __ldg(&x[blockIdx.x * (ROWS_PER_BLOCK * 128) + tid]);

    __syncthreads();

    const long long base = (long long)blockIdx.x * F4_PER_BLOCK;

    #pragma unroll
    for (int k = 0; k < ITERS; k++) {
        // pos = k*256 + tid; x index = pos>>3 = k*32 + (tid>>3)
        float xs = s_x[k * 32 + (tid >> 3)];     // broadcast across 8 lanes

        float4 wv;
        switch (k & 3) {                          // compile-time select
            case 0: wv = wr0; break;
            case 1: wv = wr1; break;
            case 2: wv = wr2; break;
            default: wv = wr3; break;
        }

        float4 r;
        r.x = xs * wv.x;
        r.y = xs * wv.y;
        r.z = xs * wv.z;
        r.w = xs * wv.w;
        __stcs(&out4[base + k * THREADS + tid], r);
    }
}

extern "C" void kernel_launch(void* const* d_in, const int* in_sizes, int n_in,
                              void* d_out, int out_size)
{
    const float*  x  = (const float*)d_in[0];
    const float4* w4 = (const float4*)d_in[1];
    float4* out4 = (float4*)d_out;

    // out_size = 512*128*4096 floats -> /4 -> /2048 per block = 32768 blocks
    int blocks = (out_size / 4) / F4_PER_BLOCK;
    csi_embedding_kernel<<<blocks, THREADS>>>(x, w4, out4);
}